// round 4
// baseline (speedup 1.0000x reference)
#include <cuda_runtime.h>
#include <cuda_bf16.h>
#include <cstdint>
#include <cstddef>

// ============================================================================
// out = x @ W'^T + b,   W' = W + 2.0 * B @ A   (LoRA folded into weights)
//   x[8192,4096] f32, W[4096,4096] f32, b[4096], A[16,4096], B[4096,16]
//
// sm_103 BASE target only (harness emits compute_103 PTX): no tcgen05, no TMA.
// Uses cp.async (sm_80) + mma.sync.m16n8k8.tf32 (legacy HMMA path).
//
// Kernel 1 (prep): W' = W + 2*B@A into 64MB __device__ scratch (~20us).
// Kernel 2 (gemm): 128x256x32 tiles, 8 warps (2x4, 64x64 each), 3-stage
//                  cp.async pipeline, stride-36 smem (conflict-free frags).
// ============================================================================

#define D_IN   4096
#define D_OUT  4096
#define RANK   16

#define BM 128
#define BN 256
#define BK 32
#define KTILES (D_IN / BK)   // 128

#define LDA 36               // smem row stride in floats (144B, 16B-aligned)
#define ASZ (BM * LDA)       // 4608 floats
#define BSZ (BN * LDA)       // 9216 floats
#define SMEM_FLOATS (3 * (ASZ + BSZ))
#define SMEM_BYTES  (SMEM_FLOATS * 4)   // 165888

__device__ float g_Wp[(size_t)D_OUT * D_IN];   // 64MB scratch for W'

// ---------------------------------------------------------------------------
static __device__ __forceinline__ uint32_t smem_u32(const void* p) {
    uint32_t a;
    asm("{ .reg .u64 t; cvta.to.shared.u64 t, %1; cvt.u32.u64 %0, t; }"
        : "=r"(a) : "l"(p));
    return a;
}

static __device__ __forceinline__ void cp_async16(uint32_t dst, const void* src) {
    asm volatile("cp.async.cg.shared.global [%0], [%1], 16;" :: "r"(dst), "l"(src));
}
#define CP_COMMIT() asm volatile("cp.async.commit_group;" ::: "memory")
#define CP_WAIT1()  asm volatile("cp.async.wait_group 1;" ::: "memory")

static __device__ __forceinline__ void mma_tf32(float c[4], const uint32_t a[4],
                                                const uint32_t b[2]) {
    asm volatile(
        "mma.sync.aligned.m16n8k8.row.col.f32.tf32.tf32.f32 "
        "{%0,%1,%2,%3}, {%4,%5,%6,%7}, {%8,%9}, {%0,%1,%2,%3};"
        : "+f"(c[0]), "+f"(c[1]), "+f"(c[2]), "+f"(c[3])
        : "r"(a[0]), "r"(a[1]), "r"(a[2]), "r"(a[3]), "r"(b[0]), "r"(b[1]));
}

// ---------------------------------------------------------------------------
// prep: W'[o,d] = W[o,d] + 2 * sum_r B[o,r] * A[r,d]
// block 256 threads: o-tile 64, d-tile 256. Thread owns column d, loops o.
// ---------------------------------------------------------------------------
__global__ __launch_bounds__(256) void prep_kernel(const float* __restrict__ W,
                                                   const float* __restrict__ A,
                                                   const float* __restrict__ Bl) {
    __shared__ float As[RANK][256];
    __shared__ float Bs[64][RANK];
    const int tid = threadIdx.x;
    const int d0 = blockIdx.x * 256, o0 = blockIdx.y * 64;

#pragma unroll
    for (int r = 0; r < RANK; ++r)
        As[r][tid] = A[(size_t)r * D_IN + d0 + tid];
#pragma unroll
    for (int i = tid; i < 64 * RANK; i += 256)
        Bs[i >> 4][i & 15] = Bl[(size_t)(o0 + (i >> 4)) * RANK + (i & 15)];
    __syncthreads();

    float a[RANK];
#pragma unroll
    for (int r = 0; r < RANK; ++r) a[r] = As[r][tid];

#pragma unroll 4
    for (int oo = 0; oo < 64; ++oo) {
        float s = 0.f;
#pragma unroll
        for (int r = 0; r < RANK; ++r) s += Bs[oo][r] * a[r];
        const size_t idx = (size_t)(o0 + oo) * D_IN + d0 + tid;
        g_Wp[idx] = W[idx] + 2.0f * s;
    }
}

// ---------------------------------------------------------------------------
// main GEMM
// ---------------------------------------------------------------------------
static __device__ __forceinline__ void stage_load(const float* __restrict__ xb,
                                                  const float* __restrict__ wb,
                                                  uint32_t aAddr, uint32_t bAddr,
                                                  int tid, int k0) {
    // A: 128 rows x 8 chunks(16B) -> 1024 chunks, 4/thread (8 threads per row)
#pragma unroll
    for (int i = 0; i < 4; ++i) {
        const int c = tid + i * 256;
        const int r = c >> 3, q = c & 7;
        cp_async16(aAddr + (uint32_t)(r * LDA + q * 4) * 4u,
                   xb + (size_t)r * D_IN + k0 + q * 4);
    }
    // B: 256 rows x 8 chunks -> 2048 chunks, 8/thread
#pragma unroll
    for (int i = 0; i < 8; ++i) {
        const int c = tid + i * 256;
        const int r = c >> 3, q = c & 7;
        cp_async16(bAddr + (uint32_t)(r * LDA + q * 4) * 4u,
                   wb + (size_t)r * D_IN + k0 + q * 4);
    }
}

__global__ __launch_bounds__(256, 1) void gemm_kernel(const float* __restrict__ x,
                                                      const float* __restrict__ bias,
                                                      float* __restrict__ out) {
    extern __shared__ float sm[];
    const uint32_t sbase = smem_u32(sm);

    const int tid = threadIdx.x;
    const int lane = tid & 31, wid = tid >> 5;
    const int wm = wid >> 2, wn = wid & 3;           // 2 x 4 warp grid
    const int m0 = blockIdx.y * BM, n0 = blockIdx.x * BN;

    const float* xb = x + (size_t)m0 * D_IN;
    const float* wb = g_Wp + (size_t)n0 * D_IN;

    float* Asm[3] = { sm, sm + ASZ, sm + 2 * ASZ };
    float* Bsm[3] = { sm + 3 * ASZ, sm + 3 * ASZ + BSZ, sm + 3 * ASZ + 2 * BSZ };
    uint32_t aA[3], bA[3];
#pragma unroll
    for (int i = 0; i < 3; ++i) {
        aA[i] = sbase + (uint32_t)(i * ASZ) * 4u;
        bA[i] = sbase + (uint32_t)(3 * ASZ + i * BSZ) * 4u;
    }

    float acc[4][8][4];
#pragma unroll
    for (int mt = 0; mt < 4; ++mt)
#pragma unroll
        for (int nt = 0; nt < 8; ++nt)
#pragma unroll
            for (int j = 0; j < 4; ++j) acc[mt][nt][j] = 0.f;

    // prologue: prefetch stages 0, 1
    stage_load(xb, wb, aA[0], bA[0], tid, 0 * BK); CP_COMMIT();
    stage_load(xb, wb, aA[1], bA[1], tid, 1 * BK); CP_COMMIT();

    const int row = lane >> 2, col = lane & 3;

    for (int s = 0; s < KTILES; ++s) {
        const int buf = s % 3;
        CP_WAIT1();          // stage s copies (this thread) done
        __syncthreads();     // all threads: stage s ready; stage s-1 reads done

        if (s + 2 < KTILES)
            stage_load(xb, wb, aA[(s + 2) % 3], bA[(s + 2) % 3], tid, (s + 2) * BK);
        CP_COMMIT();         // commit every iter (possibly empty) for uniform counts

        const float* Af = Asm[buf] + (wm * 64 + row) * LDA;
        const float* Bf = Bsm[buf] + (wn * 64 + row) * LDA;

#pragma unroll
        for (int k = 0; k < 4; ++k) {
            const int kb = k * 8 + col;
            uint32_t a[4][4], b[8][2];
#pragma unroll
            for (int mt = 0; mt < 4; ++mt) {
                const float* p = Af + mt * 16 * LDA + kb;
                a[mt][0] = __float_as_uint(p[0]);
                a[mt][1] = __float_as_uint(p[8 * LDA]);
                a[mt][2] = __float_as_uint(p[4]);
                a[mt][3] = __float_as_uint(p[8 * LDA + 4]);
            }
#pragma unroll
            for (int nt = 0; nt < 8; ++nt) {
                const float* p = Bf + nt * 8 * LDA + kb;
                b[nt][0] = __float_as_uint(p[0]);
                b[nt][1] = __float_as_uint(p[4]);
            }
#pragma unroll
            for (int mt = 0; mt < 4; ++mt)
#pragma unroll
                for (int nt = 0; nt < 8; ++nt)
                    mma_tf32(acc[mt][nt], a[mt], b[nt]);
        }
    }

    // ---- epilogue: + bias, write out ----
#pragma unroll
    for (int mt = 0; mt < 4; ++mt) {
        const int m = m0 + wm * 64 + mt * 16 + row;
#pragma unroll
        for (int nt = 0; nt < 8; ++nt) {
            const int n = n0 + wn * 64 + nt * 8 + col * 2;
            const float2 bv = *(const float2*)(bias + n);
            float2 v0, v1;
            v0.x = acc[mt][nt][0] + bv.x;
            v0.y = acc[mt][nt][1] + bv.y;
            v1.x = acc[mt][nt][2] + bv.x;
            v1.y = acc[mt][nt][3] + bv.y;
            *(float2*)(out + (size_t)m * D_OUT + n) = v0;
            *(float2*)(out + (size_t)(m + 8) * D_OUT + n) = v1;
        }
    }
}

// ---------------------------------------------------------------------------
extern "C" void kernel_launch(void* const* d_in, const int* in_sizes, int n_in,
                              void* d_out, int out_size) {
    const float* x  = (const float*)d_in[0];
    const float* W  = (const float*)d_in[1];
    const float* b  = (const float*)d_in[2];
    const float* A  = (const float*)d_in[3];
    const float* Bl = (const float*)d_in[4];
    float* out = (float*)d_out;

    const int M = in_sizes[0] / D_IN;   // 8192

    dim3 pg(D_IN / 256, D_OUT / 64);    // (16, 64)
    prep_kernel<<<pg, 256>>>(W, A, Bl);

    cudaFuncSetAttribute(gemm_kernel, cudaFuncAttributeMaxDynamicSharedMemorySize,
                         SMEM_BYTES);
    dim3 grid(D_OUT / BN, M / BM);      // (16, 64); x-fastest shares x-tiles in L2
    gemm_kernel<<<grid, 256, SMEM_BYTES>>>(x, b, out);
}

// round 5
// speedup vs baseline: 1.0887x; 1.0887x over previous
#include <cuda_runtime.h>
#include <cuda_bf16.h>
#include <cstdint>
#include <cstddef>

// ============================================================================
// out = x @ W'^T + b,   W' = W + 2.0 * B @ A   (LoRA folded into weights)
// sm_103 BASE target: cp.async + mma.sync.m16n8k8.tf32 (no tcgen05/TMA).
//
// R4 ncu: tensor=49.6%, regs=252, L2/DRAM idle -> latency-exposed frag loads.
// This round:
//  - k-groups of x and W' pre-permuted (0,4,1,5,2,6,3,7) so every MMA
//    fragment pair (k,k+4) is an aligned float2 -> LDS.64, half the LDS ops.
//  - explicit k+1 fragment prefetch (double-buffered frag registers).
//  - prep kernels round inputs to tf32 with cvt.rna (RN instead of HW RZ):
//    free accuracy margin.
// ============================================================================

#define D_IN   4096
#define D_OUT  4096
#define RANK   16

#define BM 128
#define BN 256
#define BK 32
#define KTILES (D_IN / BK)   // 128

#define LDA 40               // smem row stride in floats (160B)
#define ASZ (BM * LDA)       // 5120 floats
#define BSZ (BN * LDA)       // 10240 floats
#define SMEM_FLOATS (3 * (ASZ + BSZ))
#define SMEM_BYTES  (SMEM_FLOATS * 4)   // 184320

__device__ float g_Wp[(size_t)D_OUT * D_IN];          // permuted W' (64MB)
__device__ float g_xp[(size_t)8192 * D_IN];           // permuted x  (128MB)

// ---------------------------------------------------------------------------
static __device__ __forceinline__ uint32_t smem_u32(const void* p) {
    uint32_t a;
    asm("{ .reg .u64 t; cvta.to.shared.u64 t, %1; cvt.u32.u64 %0, t; }"
        : "=r"(a) : "l"(p));
    return a;
}

static __device__ __forceinline__ float rna_tf32(float f) {
    uint32_t r;
    asm("cvt.rna.tf32.f32 %0, %1;" : "=r"(r) : "f"(f));
    return __uint_as_float(r);
}

static __device__ __forceinline__ void cp_async16(uint32_t dst, const void* src) {
    asm volatile("cp.async.cg.shared.global [%0], [%1], 16;" :: "r"(dst), "l"(src));
}
#define CP_COMMIT() asm volatile("cp.async.commit_group;" ::: "memory")
#define CP_WAIT1()  asm volatile("cp.async.wait_group 1;" ::: "memory")

static __device__ __forceinline__ void mma_tf32(float c[4],
                                                float2 a02, float2 a13, float2 b01) {
    asm volatile(
        "mma.sync.aligned.m16n8k8.row.col.f32.tf32.tf32.f32 "
        "{%0,%1,%2,%3}, {%4,%5,%6,%7}, {%8,%9}, {%0,%1,%2,%3};"
        : "+f"(c[0]), "+f"(c[1]), "+f"(c[2]), "+f"(c[3])
        : "r"(__float_as_uint(a02.x)), "r"(__float_as_uint(a13.x)),
          "r"(__float_as_uint(a02.y)), "r"(__float_as_uint(a13.y)),
          "r"(__float_as_uint(b01.x)), "r"(__float_as_uint(b01.y)));
}

// ---------------------------------------------------------------------------
// prep_w: W'[o,perm(d)] = rna_tf32( W[o,d] + 2 * sum_r B[o,r] * A[r,d] )
// ---------------------------------------------------------------------------
__global__ __launch_bounds__(256) void prep_w_kernel(const float* __restrict__ W,
                                                     const float* __restrict__ A,
                                                     const float* __restrict__ Bl) {
    __shared__ float As[RANK][256];
    __shared__ float Bs[64][RANK];
    const int tid = threadIdx.x;
    const int d0 = blockIdx.x * 256, o0 = blockIdx.y * 64;

#pragma unroll
    for (int r = 0; r < RANK; ++r)
        As[r][tid] = A[(size_t)r * D_IN + d0 + tid];
#pragma unroll
    for (int i = tid; i < 64 * RANK; i += 256)
        Bs[i >> 4][i & 15] = Bl[(size_t)(o0 + (i >> 4)) * RANK + (i & 15)];
    __syncthreads();

    float a[RANK];
#pragma unroll
    for (int r = 0; r < RANK; ++r) a[r] = As[r][tid];

    const int d = d0 + tid;
    const int c = d & 7;
    const int pos = (d & ~7) + ((c < 4) ? (2 * c) : (2 * (c - 4) + 1));

#pragma unroll 4
    for (int oo = 0; oo < 64; ++oo) {
        float s = 0.f;
#pragma unroll
        for (int r = 0; r < RANK; ++r) s += Bs[oo][r] * a[r];
        const size_t row = (size_t)(o0 + oo) * D_IN;
        g_Wp[row + pos] = rna_tf32(W[row + d] + 2.0f * s);
    }
}

// ---------------------------------------------------------------------------
// prep_x: permute 8-float k-groups of x to (0,4,1,5,2,6,3,7), rna-round.
// ---------------------------------------------------------------------------
__global__ __launch_bounds__(256) void prep_x_kernel(const float* __restrict__ x) {
    const size_t g = (size_t)blockIdx.x * 256 + threadIdx.x;   // 8-float group id
    const size_t base = g * 8;
    const float4 u = *(const float4*)(x + base);
    const float4 v = *(const float4*)(x + base + 4);
    float4 o0, o1;
    o0.x = rna_tf32(u.x); o0.y = rna_tf32(v.x);
    o0.z = rna_tf32(u.y); o0.w = rna_tf32(v.y);
    o1.x = rna_tf32(u.z); o1.y = rna_tf32(v.z);
    o1.z = rna_tf32(u.w); o1.w = rna_tf32(v.w);
    *(float4*)(g_xp + base) = o0;
    *(float4*)(g_xp + base + 4) = o1;
}

// ---------------------------------------------------------------------------
// main GEMM
// ---------------------------------------------------------------------------
static __device__ __forceinline__ void stage_load(const float* __restrict__ xb,
                                                  const float* __restrict__ wb,
                                                  uint32_t aAddr, uint32_t bAddr,
                                                  int tid, int k0) {
#pragma unroll
    for (int i = 0; i < 4; ++i) {
        const int c = tid + i * 256;
        const int r = c >> 3, q = c & 7;
        cp_async16(aAddr + (uint32_t)(r * LDA + q * 4) * 4u,
                   xb + (size_t)r * D_IN + k0 + q * 4);
    }
#pragma unroll
    for (int i = 0; i < 8; ++i) {
        const int c = tid + i * 256;
        const int r = c >> 3, q = c & 7;
        cp_async16(bAddr + (uint32_t)(r * LDA + q * 4) * 4u,
                   wb + (size_t)r * D_IN + k0 + q * 4);
    }
}

__global__ __launch_bounds__(256, 1) void gemm_kernel(const float* __restrict__ bias,
                                                      float* __restrict__ out) {
    extern __shared__ float sm[];
    const uint32_t sbase = smem_u32(sm);

    const int tid = threadIdx.x;
    const int lane = tid & 31, wid = tid >> 5;
    const int wm = wid >> 2, wn = wid & 3;           // 2 x 4 warp grid
    const int m0 = blockIdx.y * BM, n0 = blockIdx.x * BN;

    const float* xb = g_xp + (size_t)m0 * D_IN;
    const float* wb = g_Wp + (size_t)n0 * D_IN;

    float* Asm[3] = { sm, sm + ASZ, sm + 2 * ASZ };
    float* Bsm[3] = { sm + 3 * ASZ, sm + 3 * ASZ + BSZ, sm + 3 * ASZ + 2 * BSZ };
    uint32_t aA[3], bA[3];
#pragma unroll
    for (int i = 0; i < 3; ++i) {
        aA[i] = sbase + (uint32_t)(i * ASZ) * 4u;
        bA[i] = sbase + (uint32_t)(3 * ASZ + i * BSZ) * 4u;
    }

    float acc[4][8][4];
#pragma unroll
    for (int mt = 0; mt < 4; ++mt)
#pragma unroll
        for (int nt = 0; nt < 8; ++nt)
#pragma unroll
            for (int j = 0; j < 4; ++j) acc[mt][nt][j] = 0.f;

    stage_load(xb, wb, aA[0], bA[0], tid, 0 * BK); CP_COMMIT();
    stage_load(xb, wb, aA[1], bA[1], tid, 1 * BK); CP_COMMIT();

    const int row = lane >> 2, col = lane & 3;

    // frag double buffers (float2 pairs: (k, k+4))
    float2 fa0[2][4], fa1[2][4], fb[2][8];

    for (int s = 0; s < KTILES; ++s) {
        const int buf = s % 3;
        CP_WAIT1();
        __syncthreads();

        if (s + 2 < KTILES)
            stage_load(xb, wb, aA[(s + 2) % 3], bA[(s + 2) % 3], tid, (s + 2) * BK);
        CP_COMMIT();

        // float2 views of this warp's sub-tiles
        const float2* Af = (const float2*)(Asm[buf] + (wm * 64 + row) * LDA);
        const float2* Bf = (const float2*)(Bsm[buf] + (wn * 64 + row) * LDA);
        // float2 strides: 16 rows = 16*LDA/2 = 320 ; 8 rows = 160

#define LDFRAG(kk, pb) do {                                                    \
        const int fo = 4 * (kk) + col;                                         \
        _Pragma("unroll")                                                      \
        for (int mt = 0; mt < 4; ++mt) {                                       \
            fa0[pb][mt] = Af[mt * 320 + fo];                                   \
            fa1[pb][mt] = Af[mt * 320 + 160 + fo];                             \
        }                                                                      \
        _Pragma("unroll")                                                      \
        for (int nt = 0; nt < 8; ++nt)                                         \
            fb[pb][nt] = Bf[nt * 160 + fo];                                    \
    } while (0)

        LDFRAG(0, 0);
#pragma unroll
        for (int k = 0; k < 4; ++k) {
            const int pb = k & 1;
            if (k < 3) LDFRAG(k + 1, pb ^ 1);
#pragma unroll
            for (int mt = 0; mt < 4; ++mt)
#pragma unroll
                for (int nt = 0; nt < 8; ++nt)
                    mma_tf32(acc[mt][nt], fa0[pb][mt], fa1[pb][mt], fb[pb][nt]);
        }
#undef LDFRAG
    }

    // ---- epilogue: + bias, write out ----
#pragma unroll
    for (int mt = 0; mt < 4; ++mt) {
        const int m = m0 + wm * 64 + mt * 16 + row;
#pragma unroll
        for (int nt = 0; nt < 8; ++nt) {
            const int n = n0 + wn * 64 + nt * 8 + col * 2;
            const float2 bv = *(const float2*)(bias + n);
            float2 v0, v1;
            v0.x = acc[mt][nt][0] + bv.x;
            v0.y = acc[mt][nt][1] + bv.y;
            v1.x = acc[mt][nt][2] + bv.x;
            v1.y = acc[mt][nt][3] + bv.y;
            *(float2*)(out + (size_t)m * D_OUT + n) = v0;
            *(float2*)(out + (size_t)(m + 8) * D_OUT + n) = v1;
        }
    }
}

// ---------------------------------------------------------------------------
extern "C" void kernel_launch(void* const* d_in, const int* in_sizes, int n_in,
                              void* d_out, int out_size) {
    const float* x  = (const float*)d_in[0];
    const float* W  = (const float*)d_in[1];
    const float* b  = (const float*)d_in[2];
    const float* A  = (const float*)d_in[3];
    const float* Bl = (const float*)d_in[4];
    float* out = (float*)d_out;

    const int M = in_sizes[0] / D_IN;   // 8192

    dim3 pg(D_IN / 256, D_OUT / 64);    // (16, 64)
    prep_w_kernel<<<pg, 256>>>(W, A, Bl);
    prep_x_kernel<<<(unsigned)((size_t)M * D_IN / 8 / 256), 256>>>(x);

    cudaFuncSetAttribute(gemm_kernel, cudaFuncAttributeMaxDynamicSharedMemorySize,
                         SMEM_BYTES);
    dim3 grid(D_OUT / BN, M / BM);      // (16, 64); x-fastest shares x-tiles in L2
    gemm_kernel<<<grid, 256, SMEM_BYTES>>>(b, out);
}

// round 15
// speedup vs baseline: 1.1333x; 1.0410x over previous
#include <cuda_runtime.h>
#include <cuda_bf16.h>
#include <cstdint>
#include <cstddef>

// ============================================================================
// out = x @ W'^T + b,   W' = W + 2.0 * B @ A   (LoRA folded into weights)
// sm_103 BASE target: cp.async + mma.sync.m16n8k8.tf32 (no tcgen05/TMA).
//
// R4/R5 evidence: tensor pipe ~50% idle, regs at ceiling, L2/DRAM idle.
// This round: occupancy instead of registers.
//  - CTA tile 128x128 (was 128x256), warp tile 64x32 -> acc 64 regs.
//  - 2 CTAs/SM (__launch_bounds__(256,2)), 2-stage pipeline, 80KB smem/CTA.
//  - 4 warps/SMSP hide LDS latency; no intra-warp frag buffering.
//  - keep: permuted (k,k+4) float2 layout, rna tf32 rounding in prep.
// ============================================================================

#define D_IN   4096
#define D_OUT  4096
#define RANK   16

#define BM 128
#define BN 128
#define BK 32
#define KTILES (D_IN / BK)   // 128

#define LDA 40               // smem row stride in floats (160B)
#define ASZ (BM * LDA)       // 5120 floats
#define BSZ (BN * LDA)       // 5120 floats
#define SMEM_FLOATS (2 * (ASZ + BSZ))
#define SMEM_BYTES  (SMEM_FLOATS * 4)   // 81920 (80KB per CTA)

__device__ float g_Wp[(size_t)D_OUT * D_IN];          // permuted W' (64MB)
__device__ float g_xp[(size_t)8192 * D_IN];           // permuted x  (128MB)

// ---------------------------------------------------------------------------
static __device__ __forceinline__ uint32_t smem_u32(const void* p) {
    uint32_t a;
    asm("{ .reg .u64 t; cvta.to.shared.u64 t, %1; cvt.u32.u64 %0, t; }"
        : "=r"(a) : "l"(p));
    return a;
}

static __device__ __forceinline__ float rna_tf32(float f) {
    uint32_t r;
    asm("cvt.rna.tf32.f32 %0, %1;" : "=r"(r) : "f"(f));
    return __uint_as_float(r);
}

static __device__ __forceinline__ void cp_async16(uint32_t dst, const void* src) {
    asm volatile("cp.async.cg.shared.global [%0], [%1], 16;" :: "r"(dst), "l"(src));
}
#define CP_COMMIT() asm volatile("cp.async.commit_group;" ::: "memory")
#define CP_WAIT1()  asm volatile("cp.async.wait_group 1;" ::: "memory")

static __device__ __forceinline__ void mma_tf32(float c[4],
                                                float2 a02, float2 a13, float2 b01) {
    asm volatile(
        "mma.sync.aligned.m16n8k8.row.col.f32.tf32.tf32.f32 "
        "{%0,%1,%2,%3}, {%4,%5,%6,%7}, {%8,%9}, {%0,%1,%2,%3};"
        : "+f"(c[0]), "+f"(c[1]), "+f"(c[2]), "+f"(c[3])
        : "r"(__float_as_uint(a02.x)), "r"(__float_as_uint(a13.x)),
          "r"(__float_as_uint(a02.y)), "r"(__float_as_uint(a13.y)),
          "r"(__float_as_uint(b01.x)), "r"(__float_as_uint(b01.y)));
}

// ---------------------------------------------------------------------------
// prep_w: W'[o,perm(d)] = rna_tf32( W[o,d] + 2 * sum_r B[o,r] * A[r,d] )
// ---------------------------------------------------------------------------
__global__ __launch_bounds__(256) void prep_w_kernel(const float* __restrict__ W,
                                                     const float* __restrict__ A,
                                                     const float* __restrict__ Bl) {
    __shared__ float As[RANK][256];
    __shared__ float Bs[64][RANK];
    const int tid = threadIdx.x;
    const int d0 = blockIdx.x * 256, o0 = blockIdx.y * 64;

#pragma unroll
    for (int r = 0; r < RANK; ++r)
        As[r][tid] = A[(size_t)r * D_IN + d0 + tid];
#pragma unroll
    for (int i = tid; i < 64 * RANK; i += 256)
        Bs[i >> 4][i & 15] = Bl[(size_t)(o0 + (i >> 4)) * RANK + (i & 15)];
    __syncthreads();

    float a[RANK];
#pragma unroll
    for (int r = 0; r < RANK; ++r) a[r] = As[r][tid];

    const int d = d0 + tid;
    const int c = d & 7;
    const int pos = (d & ~7) + ((c < 4) ? (2 * c) : (2 * (c - 4) + 1));

#pragma unroll 4
    for (int oo = 0; oo < 64; ++oo) {
        float s = 0.f;
#pragma unroll
        for (int r = 0; r < RANK; ++r) s += Bs[oo][r] * a[r];
        const size_t row = (size_t)(o0 + oo) * D_IN;
        g_Wp[row + pos] = rna_tf32(W[row + d] + 2.0f * s);
    }
}

// ---------------------------------------------------------------------------
// prep_x: permute 8-float k-groups of x to (0,4,1,5,2,6,3,7), rna-round.
// ---------------------------------------------------------------------------
__global__ __launch_bounds__(256) void prep_x_kernel(const float* __restrict__ x) {
    const size_t g = (size_t)blockIdx.x * 256 + threadIdx.x;   // 8-float group id
    const size_t base = g * 8;
    const float4 u = *(const float4*)(x + base);
    const float4 v = *(const float4*)(x + base + 4);
    float4 o0, o1;
    o0.x = rna_tf32(u.x); o0.y = rna_tf32(v.x);
    o0.z = rna_tf32(u.y); o0.w = rna_tf32(v.y);
    o1.x = rna_tf32(u.z); o1.y = rna_tf32(v.z);
    o1.z = rna_tf32(u.w); o1.w = rna_tf32(v.w);
    *(float4*)(g_xp + base) = o0;
    *(float4*)(g_xp + base + 4) = o1;
}

// ---------------------------------------------------------------------------
// main GEMM: 128x128x32 tiles, 8 warps (2x4, 64x32 each), 2-stage, 2 CTA/SM
// ---------------------------------------------------------------------------
static __device__ __forceinline__ void stage_load(const float* __restrict__ xb,
                                                  const float* __restrict__ wb,
                                                  uint32_t aAddr, uint32_t bAddr,
                                                  int tid, int k0) {
    // A: 128 rows x 8 chunks(16B) = 1024 chunks, 4/thread
#pragma unroll
    for (int i = 0; i < 4; ++i) {
        const int c = tid + i * 256;
        const int r = c >> 3, q = c & 7;
        cp_async16(aAddr + (uint32_t)(r * LDA + q * 4) * 4u,
                   xb + (size_t)r * D_IN + k0 + q * 4);
    }
    // B: 128 rows x 8 chunks = 1024 chunks, 4/thread
#pragma unroll
    for (int i = 0; i < 4; ++i) {
        const int c = tid + i * 256;
        const int r = c >> 3, q = c & 7;
        cp_async16(bAddr + (uint32_t)(r * LDA + q * 4) * 4u,
                   wb + (size_t)r * D_IN + k0 + q * 4);
    }
}

__global__ __launch_bounds__(256, 2) void gemm_kernel(const float* __restrict__ bias,
                                                      float* __restrict__ out) {
    extern __shared__ float sm[];
    const uint32_t sbase = smem_u32(sm);

    const int tid = threadIdx.x;
    const int lane = tid & 31, wid = tid >> 5;
    const int wm = wid >> 2, wn = wid & 3;           // 2 x 4 warp grid (64 x 32)
    const int m0 = blockIdx.y * BM, n0 = blockIdx.x * BN;

    const float* xb = g_xp + (size_t)m0 * D_IN;
    const float* wb = g_Wp + (size_t)n0 * D_IN;

    float* Asm[2] = { sm, sm + ASZ };
    float* Bsm[2] = { sm + 2 * ASZ, sm + 2 * ASZ + BSZ };
    uint32_t aA[2], bA[2];
#pragma unroll
    for (int i = 0; i < 2; ++i) {
        aA[i] = sbase + (uint32_t)(i * ASZ) * 4u;
        bA[i] = sbase + (uint32_t)(2 * ASZ + i * BSZ) * 4u;
    }

    float acc[4][4][4];
#pragma unroll
    for (int mt = 0; mt < 4; ++mt)
#pragma unroll
        for (int nt = 0; nt < 4; ++nt)
#pragma unroll
            for (int j = 0; j < 4; ++j) acc[mt][nt][j] = 0.f;

    stage_load(xb, wb, aA[0], bA[0], tid, 0 * BK); CP_COMMIT();
    stage_load(xb, wb, aA[1], bA[1], tid, 1 * BK); CP_COMMIT();

    const int row = lane >> 2, col = lane & 3;

    for (int s = 0; s < KTILES; ++s) {
        const int buf = s & 1;
        CP_WAIT1();          // stage s resident (this thread's view)
        __syncthreads();     // all threads: stage s ready

        // float2 views of this warp's sub-tiles; strides in float2:
        //   16 rows = 16*LDA/2 = 320 ; 8 rows = 160
        const float2* Af = (const float2*)(Asm[buf] + (wm * 64 + row) * LDA);
        const float2* Bf = (const float2*)(Bsm[buf] + (wn * 32 + row) * LDA);

#pragma unroll
        for (int k = 0; k < 4; ++k) {
            const int fo = 4 * k + col;
            float2 fa0[4], fa1[4], fb[4];
#pragma unroll
            for (int mt = 0; mt < 4; ++mt) {
                fa0[mt] = Af[mt * 320 + fo];
                fa1[mt] = Af[mt * 320 + 160 + fo];
            }
#pragma unroll
            for (int nt = 0; nt < 4; ++nt)
                fb[nt] = Bf[nt * 160 + fo];
#pragma unroll
            for (int mt = 0; mt < 4; ++mt)
#pragma unroll
                for (int nt = 0; nt < 4; ++nt)
                    mma_tf32(acc[mt][nt], fa0[mt], fa1[mt], fb[nt]);
        }

        __syncthreads();     // all warps done reading buf before overwrite
        if (s + 2 < KTILES)
            stage_load(xb, wb, aA[buf], bA[buf], tid, (s + 2) * BK);
        CP_COMMIT();         // uniform group accounting (possibly empty)
    }

    // ---- epilogue: + bias, write out ----
#pragma unroll
    for (int mt = 0; mt < 4; ++mt) {
        const int m = m0 + wm * 64 + mt * 16 + row;
#pragma unroll
        for (int nt = 0; nt < 4; ++nt) {
            const int n = n0 + wn * 32 + nt * 8 + col * 2;
            const float2 bv = *(const float2*)(bias + n);
            float2 v0, v1;
            v0.x = acc[mt][nt][0] + bv.x;
            v0.y = acc[mt][nt][1] + bv.y;
            v1.x = acc[mt][nt][2] + bv.x;
            v1.y = acc[mt][nt][3] + bv.y;
            *(float2*)(out + (size_t)m * D_OUT + n) = v0;
            *(float2*)(out + (size_t)(m + 8) * D_OUT + n) = v1;
        }
    }
}

// ---------------------------------------------------------------------------
extern "C" void kernel_launch(void* const* d_in, const int* in_sizes, int n_in,
                              void* d_out, int out_size) {
    const float* x  = (const float*)d_in[0];
    const float* W  = (const float*)d_in[1];
    const float* b  = (const float*)d_in[2];
    const float* A  = (const float*)d_in[3];
    const float* Bl = (const float*)d_in[4];
    float* out = (float*)d_out;

    const int M = in_sizes[0] / D_IN;   // 8192

    dim3 pg(D_IN / 256, D_OUT / 64);    // (16, 64)
    prep_w_kernel<<<pg, 256>>>(W, A, Bl);
    prep_x_kernel<<<(unsigned)((size_t)M * D_IN / 8 / 256), 256>>>(x);

    cudaFuncSetAttribute(gemm_kernel, cudaFuncAttributeMaxDynamicSharedMemorySize,
                         SMEM_BYTES);
    dim3 grid(D_OUT / BN, M / BM);      // (32, 64); x-fastest shares x-tiles in L2
    gemm_kernel<<<grid, 256, SMEM_BYTES>>>(b, out);
}